// round 13
// baseline (speedup 1.0000x reference)
#include <cuda_runtime.h>

// OrbitalAEVComputer: coefficients [64,256,45] f32 -> out [64,256,4608] f32
// Per (conf,atom): 12 AOVs (4 p + 8 reordered d), radial 12*32, angular 66*8*8.

#define NBLOCKS (64 * 256)
#define OUT_STRIDE 4608
#define NPAIR 66

// cos/sin of shfZ = linspace(0.19634954, 2.94524311, 8)  (odd multiples of pi/16)
__constant__ float COSZ[8] = {
     0.98078528f,  0.83146961f,  0.55557023f,  0.19509032f,
    -0.19509032f, -0.55557023f, -0.83146961f, -0.98078528f
};
__constant__ float SINZ[8] = {
     0.19509032f,  0.55557023f,  0.83146961f,  0.98078528f,
     0.98078528f,  0.83146961f,  0.55557023f,  0.19509032f
};

// triu_indices(12, k=1), i-major
__constant__ unsigned char IU[NPAIR] = {
    0,0,0,0,0,0,0,0,0,0,0,
    1,1,1,1,1,1,1,1,1,1,
    2,2,2,2,2,2,2,2,2,
    3,3,3,3,3,3,3,3,
    4,4,4,4,4,4,4,
    5,5,5,5,5,5,
    6,6,6,6,6,
    7,7,7,7,
    8,8,8,
    9,9,
    10
};
__constant__ unsigned char JU[NPAIR] = {
    1,2,3,4,5,6,7,8,9,10,11,
    2,3,4,5,6,7,8,9,10,11,
    3,4,5,6,7,8,9,10,11,
    4,5,6,7,8,9,10,11,
    5,6,7,8,9,10,11,
    6,7,8,9,10,11,
    7,8,9,10,11,
    8,9,10,11,
    9,10,11,
    10,11,
    11
};

// 256-bit store (sm_100+): one instruction writes a full 32B row; lanes at 32B
// stride -> 1024B dense per warp = 8 wavefronts (the minimum).
__device__ __forceinline__ void stg256(float* p,
                                       float v0, float v1, float v2, float v3,
                                       float v4, float v5, float v6, float v7)
{
    asm volatile("st.global.v8.f32 [%0], {%1,%2,%3,%4,%5,%6,%7,%8};"
                 :: "l"(p), "f"(v0), "f"(v1), "f"(v2), "f"(v3),
                           "f"(v4), "f"(v5), "f"(v6), "f"(v7)
                 : "memory");
}

__device__ __forceinline__ float ex2(float x)
{
    float r;
    asm("ex2.approx.ftz.f32 %0, %1;" : "=f"(r) : "f"(x));
    return r;
}
__device__ __forceinline__ float lg2(float x)
{
    float r;
    asm("lg2.approx.f32 %0, %1;" : "=f"(r) : "f"(x));
    return r;
}

#define NEG8_LOG2E (-11.5416473f)   // -8 * log2(e)

// One angular task: pair p = m>>3, z-row = m&7 (cosz/sinz hoisted by caller).
// Output row = 2*((1+cos(angle-shfZ))/2)^32 * exp(-8(av-shfA)^2), computed
// entirely in log2 domain: one LG2 + 8 EX2, no pow chain, no g*f multiplies.
__device__ __forceinline__ void angular_task(float* __restrict__ o,
                                             const float4* __restrict__ pairsh,
                                             int m, float cosz, float sinz)
{
    int p = m >> 3;
    float4 cs = pairsh[p];                        // 8-way broadcast LDS.128

    // cos(angle - shfZ) = cz*cosZ + sqrt(1-cz^2)*sinZ (exact identity)
    float cosd = fmaf(cs.x, cosz, cs.y * sinz);
    float b = fmaf(0.5f, cosd, 0.5f);             // (1+cosd)/2 in [0,1]
    float lg = fmaf(32.0f, lg2(b), 1.0f);         // log2(2 * b^32); b=0 -> -inf

    float av = cs.z;
    float v[8];
    #pragma unroll
    for (int a = 0; a < 8; a++) {
        float ua = av - (0.5f + (3.0f / 7.0f) * (float)a);
        v[a] = ex2(fmaf(ua * ua, NEG8_LOG2E, lg));
    }
    stg256(o + 384 + (m << 3),
           v[0], v[1], v[2], v[3], v[4], v[5], v[6], v[7]);
}

__global__ __launch_bounds__(128, 12)
void orbital_aev_kernel(const float* __restrict__ coeff, float* __restrict__ out)
{
    __shared__ float  dsh[12];
    __shared__ float  nvsh[12][3];
    __shared__ float4 pairsh[NPAIR];   // (cz = 0.95*cos, sz = sqrt(1-cz^2), avdist, 0)

    const int t = threadIdx.x;
    const float* __restrict__ c = coeff + (size_t)blockIdx.x * 45;
    float* __restrict__ o = out + (size_t)blockIdx.x * OUT_STRIDE;

    // ---- Build 12 AOVs: dist + normalized vectors into SMEM ----
    if (t < 12) {
        float x, y, z;
        if (t < 4) {
            int b = 9 + 3 * t;
            x = c[b]; y = c[b + 1]; z = c[b + 2];
        } else {
            int r = (t - 4) >> 1;
            int b = 21 + 6 * r;
            if (((t - 4) & 1) == 0) {        // d row picks [0,2,5]
                x = c[b];     y = c[b + 2]; z = c[b + 5];
            } else {                          // then [4,3,1]
                x = c[b + 4]; y = c[b + 3]; z = c[b + 1];
            }
        }
        float s = x * x + y * y + z * z;
        float inv, d;
        if (s > 1e-24f) { inv = rsqrtf(s); d = s * inv; }
        else            { inv = 0.0f;      d = 0.0f;    }
        dsh[t] = d;
        nvsh[t][0] = x * inv;
        nvsh[t][1] = y * inv;
        nvsh[t][2] = z * inv;
    }
    __syncthreads();

    // ---- Middle phase: DISJOINT thread ranges run concurrently. ----
    // Threads [0,66): pair terms cz/sz/avdist into SMEM.
    // Threads [66,114): radial outputs (s_aev == r_aev; 48 x STG.256).
    if (t < NPAIR) {
        int i = IU[t], j = JU[t];
        float cc = nvsh[i][0] * nvsh[j][0]
                 + nvsh[i][1] * nvsh[j][1]
                 + nvsh[i][2] * nvsh[j][2];
        float cz = 0.95f * cc;
        float sz = sqrtf(fmaxf(0.0f, 1.0f - cz * cz));
        float av = 0.5f * (dsh[i] + dsh[j]);
        pairsh[t] = make_float4(cz, sz, av, 0.0f);
    } else if (t < NPAIR + 48) {
        int r   = t - NPAIR;
        int aov = r >> 2;
        int q   = r & 3;
        float d  = dsh[aov];
        int   kb = (q & 1) << 3;
        float v[8];
        #pragma unroll
        for (int j = 0; j < 8; j++) {
            float u = d - (0.5f + 0.2f * (float)(kb + j));
            v[j] = __expf(-16.0f * u * u);
        }
        stg256(o + (aov << 5) + (q << 3),
               v[0], v[1], v[2], v[3], v[4], v[5], v[6], v[7]);
    }
    __syncthreads();

    // ---- Angular: 528 row-tasks (pair p, z = m&7 = t&7 thread-invariant).
    //      Iterations 0-3 are unconditional (t+384 <= 511 < 528); 16-thread tail. ----
    const float cosz = COSZ[t & 7];
    const float sinz = SINZ[t & 7];
    #pragma unroll
    for (int iter = 0; iter < 4; iter++)
        angular_task(o, pairsh, t + 128 * iter, cosz, sinz);
    if (t < 16)
        angular_task(o, pairsh, t + 512, cosz, sinz);
}

extern "C" void kernel_launch(void* const* d_in, const int* in_sizes, int n_in,
                              void* d_out, int out_size)
{
    const float* coeff = (const float*)d_in[0];
    float* out = (float*)d_out;
    orbital_aev_kernel<<<NBLOCKS, 128>>>(coeff, out);
}

// round 16
// speedup vs baseline: 1.2910x; 1.2910x over previous
#include <cuda_runtime.h>

// OrbitalAEVComputer: coefficients [64,256,45] f32 -> out [64,256,4608] f32
// Per (conf,atom): 12 AOVs (4 p + 8 reordered d), radial 12*32, angular 66*8*8.

#define NBLOCKS (64 * 256)
#define OUT_STRIDE 4608
#define NPAIR 66

// cos/sin of shfZ = linspace(0.19634954, 2.94524311, 8)  (odd multiples of pi/16)
__constant__ float COSZ[8] = {
     0.98078528f,  0.83146961f,  0.55557023f,  0.19509032f,
    -0.19509032f, -0.55557023f, -0.83146961f, -0.98078528f
};
__constant__ float SINZ[8] = {
     0.19509032f,  0.55557023f,  0.83146961f,  0.98078528f,
     0.98078528f,  0.83146961f,  0.55557023f,  0.19509032f
};

// triu_indices(12, k=1), i-major
__constant__ unsigned char IU[NPAIR] = {
    0,0,0,0,0,0,0,0,0,0,0,
    1,1,1,1,1,1,1,1,1,1,
    2,2,2,2,2,2,2,2,2,
    3,3,3,3,3,3,3,3,
    4,4,4,4,4,4,4,
    5,5,5,5,5,5,
    6,6,6,6,6,
    7,7,7,7,
    8,8,8,
    9,9,
    10
};
__constant__ unsigned char JU[NPAIR] = {
    1,2,3,4,5,6,7,8,9,10,11,
    2,3,4,5,6,7,8,9,10,11,
    3,4,5,6,7,8,9,10,11,
    4,5,6,7,8,9,10,11,
    5,6,7,8,9,10,11,
    6,7,8,9,10,11,
    7,8,9,10,11,
    8,9,10,11,
    9,10,11,
    10,11,
    11
};

// 256-bit store (sm_100+): one instruction writes a full 32B row; lanes at 32B
// stride -> 1024B dense per warp = 8 wavefronts (the minimum).
__device__ __forceinline__ void stg256(float* p,
                                       float v0, float v1, float v2, float v3,
                                       float v4, float v5, float v6, float v7)
{
    asm volatile("st.global.v8.f32 [%0], {%1,%2,%3,%4,%5,%6,%7,%8};"
                 :: "l"(p), "f"(v0), "f"(v1), "f"(v2), "f"(v3),
                           "f"(v4), "f"(v5), "f"(v6), "f"(v7)
                 : "memory");
}

__device__ __forceinline__ float ex2(float x)
{
    float r;
    asm("ex2.approx.ftz.f32 %0, %1;" : "=f"(r) : "f"(x));
    return r;
}
__device__ __forceinline__ float lg2(float x)
{
    float r;
    asm("lg2.approx.f32 %0, %1;" : "=f"(r) : "f"(x));
    return r;
}

#define NEG8_LOG2E (-11.5416473f)   // -8 * log2(e)

// One angular task: pair p = m>>3, z-row = m&7 (cosz/sinz hoisted by caller).
// Output row = 2*((1+cos(angle-shfZ))/2)^32 * exp(-8(av-shfA)^2), computed
// entirely in log2 domain: one LG2 + 8 EX2, no pow chain, no g*f multiplies.
__device__ __forceinline__ void angular_task(float* __restrict__ o,
                                             const float4* __restrict__ pairsh,
                                             int m, float cosz, float sinz)
{
    int p = m >> 3;
    float4 cs = pairsh[p];                        // 8-way broadcast LDS.128

    // cos(angle - shfZ) = cz*cosZ + sqrt(1-cz^2)*sinZ (exact identity)
    float cosd = fmaf(cs.x, cosz, cs.y * sinz);
    float b = fmaf(0.5f, cosd, 0.5f);             // (1+cosd)/2 in [0,1]
    float lg = fmaf(32.0f, lg2(b), 1.0f);         // log2(2 * b^32); b=0 -> -inf

    float av = cs.z;
    float v[8];
    #pragma unroll
    for (int a = 0; a < 8; a++) {
        float ua = av - (0.5f + (3.0f / 7.0f) * (float)a);
        v[a] = ex2(fmaf(ua * ua, NEG8_LOG2E, lg));
    }
    stg256(o + 384 + (m << 3),
           v[0], v[1], v[2], v[3], v[4], v[5], v[6], v[7]);
}

__global__ __launch_bounds__(128, 10)
void orbital_aev_kernel(const float* __restrict__ coeff, float* __restrict__ out)
{
    __shared__ float  dsh[12];
    __shared__ float  nvsh[12][3];
    __shared__ float4 pairsh[NPAIR];   // (cz = 0.95*cos, sz = sqrt(1-cz^2), avdist, 0)

    const int t = threadIdx.x;
    const float* __restrict__ c = coeff + (size_t)blockIdx.x * 45;
    float* __restrict__ o = out + (size_t)blockIdx.x * OUT_STRIDE;

    // ---- Build 12 AOVs: dist + normalized vectors into SMEM ----
    if (t < 12) {
        float x, y, z;
        if (t < 4) {
            int b = 9 + 3 * t;
            x = c[b]; y = c[b + 1]; z = c[b + 2];
        } else {
            int r = (t - 4) >> 1;
            int b = 21 + 6 * r;
            if (((t - 4) & 1) == 0) {        // d row picks [0,2,5]
                x = c[b];     y = c[b + 2]; z = c[b + 5];
            } else {                          // then [4,3,1]
                x = c[b + 4]; y = c[b + 3]; z = c[b + 1];
            }
        }
        float s = x * x + y * y + z * z;
        float inv, d;
        if (s > 1e-24f) { inv = rsqrtf(s); d = s * inv; }
        else            { inv = 0.0f;      d = 0.0f;    }
        dsh[t] = d;
        nvsh[t][0] = x * inv;
        nvsh[t][1] = y * inv;
        nvsh[t][2] = z * inv;
    }
    __syncthreads();

    // ---- Middle phase: DISJOINT thread ranges run concurrently. ----
    // Threads [0,66): pair terms cz/sz/avdist into SMEM.
    // Threads [66,114): radial outputs (s_aev == r_aev; 48 x STG.256).
    if (t < NPAIR) {
        int i = IU[t], j = JU[t];
        float cc = nvsh[i][0] * nvsh[j][0]
                 + nvsh[i][1] * nvsh[j][1]
                 + nvsh[i][2] * nvsh[j][2];
        float cz = 0.95f * cc;
        float sz = sqrtf(fmaxf(0.0f, 1.0f - cz * cz));
        float av = 0.5f * (dsh[i] + dsh[j]);
        pairsh[t] = make_float4(cz, sz, av, 0.0f);
    } else if (t < NPAIR + 48) {
        int r   = t - NPAIR;
        int aov = r >> 2;
        int q   = r & 3;
        float d  = dsh[aov];
        int   kb = (q & 1) << 3;
        float v[8];
        #pragma unroll
        for (int j = 0; j < 8; j++) {
            float u = d - (0.5f + 0.2f * (float)(kb + j));
            v[j] = __expf(-16.0f * u * u);
        }
        stg256(o + (aov << 5) + (q << 3),
               v[0], v[1], v[2], v[3], v[4], v[5], v[6], v[7]);
    }
    __syncthreads();

    // ---- Angular: 528 row-tasks (pair p, z = m&7 = t&7 thread-invariant).
    //      Iterations 0-3 are unconditional (t+384 <= 511 < 528); 16-thread tail. ----
    const float cosz = COSZ[t & 7];
    const float sinz = SINZ[t & 7];
    #pragma unroll
    for (int iter = 0; iter < 4; iter++)
        angular_task(o, pairsh, t + 128 * iter, cosz, sinz);
    if (t < 16)
        angular_task(o, pairsh, t + 512, cosz, sinz);
}

extern "C" void kernel_launch(void* const* d_in, const int* in_sizes, int n_in,
                              void* d_out, int out_size)
{
    const float* coeff = (const float*)d_in[0];
    float* out = (float*)d_out;
    orbital_aev_kernel<<<NBLOCKS, 128>>>(coeff, out);
}